// round 17
// baseline (speedup 1.0000x reference)
#include <cuda_runtime.h>
#include <stdint.h>

// Wavelet denoising: 3-level Haar DWT, soft-threshold (exact median of |cd1|),
// inverse DWT. Rows of L=1024, warp-per-row, cyclic float4 layout.
//
// R17: cp.async (LDGSTS) software prefetch of the NEXT row into a per-warp
// 4KB smem buffer — zero register cost — so loads stay in flight during the
// median search. Park buffer (cd2/ca3/cd3) stays in smem as in R16. Grid-
// stride, ~4 rows per warp. Median is EXACT; transform unnormalized with
// scales folded into thresholds / final FMAs.

__device__ __forceinline__ void cp16(void* smem_dst, const void* gsrc) {
    unsigned s = (unsigned)__cvta_generic_to_shared(smem_dst);
    asm volatile("cp.async.cg.shared.global [%0], [%1], 16;"
                 :: "r"(s), "l"(gsrc) : "memory");
}
__device__ __forceinline__ void cp_commit() {
    asm volatile("cp.async.commit_group;" ::: "memory");
}
__device__ __forceinline__ void cp_wait_all() {
    asm volatile("cp.async.wait_group 0;" ::: "memory");
}

__global__ __launch_bounds__(256, 4) void wavelet_rows_kernel(
    const float* __restrict__ x, float* __restrict__ out, int nrows)
{
    extern __shared__ float4 dsm[];
    const int warp = threadIdx.x >> 5;
    const int lane = threadIdx.x & 31;

    float4* buf  = dsm + warp * 256;                               // 4KB/warp
    float*  park = reinterpret_cast<float*>(dsm + 2048) + warp * (24 * 32);

    const int warps_total = gridDim.x * 8;
    int row = blockIdx.x * 8 + warp;
    if (row >= nrows) return;

    const float4* __restrict__ xb = reinterpret_cast<const float4*>(x);
    float4* __restrict__ ob       = reinterpret_cast<float4*>(out);

    // initial prefetch of first row
    {
        const float4* xr = xb + (size_t)row * 256;
#pragma unroll
        for (int i = 0; i < 8; i++) cp16(&buf[i * 32 + lane], &xr[i * 32 + lane]);
        cp_commit();
    }

    while (true) {
        const int nxt = row + warps_total;
        cp_wait_all();   // current row resident in buf

        // ---- levels 1+2+3 (unnormalized), park cd2/ca3/cd3 in smem ----
        float cd1[16];
#pragma unroll
        for (int i = 0; i < 8; i++) {
            float4 v = buf[i * 32 + lane];
            float a = v.x + v.y;
            cd1[2*i]   = v.x - v.y;
            float b = v.z + v.w;
            cd1[2*i+1] = v.z - v.w;
            float ca2 = a + b;
            float cd2 = a - b;
            float nb = __shfl_down_sync(0xffffffffu, ca2, 1);   // level 3 (even lanes)
            park[(i)      * 32 + lane] = cd2;
            park[(8 + i)  * 32 + lane] = ca2 + nb;   // ca3
            park[(16 + i) * 32 + lane] = ca2 - nb;   // cd3
        }

        // ---- prefetch next row (register-free; hides behind median loop) ----
        if (nxt < nrows) {
            const float4* xn = xb + (size_t)nxt * 256;
#pragma unroll
            for (int i = 0; i < 8; i++) cp16(&buf[i * 32 + lane], &xn[i * 32 + lane]);
            cp_commit();
        }

        // ============ exact median of |cd1'| (512 values, warp-wide) ==========
        float s = 0.f;
#pragma unroll
        for (int i = 0; i < 16; i++) s += fabsf(cd1[i]);
#pragma unroll
        for (int d = 16; d; d >>= 1) s += __shfl_xor_sync(0xffffffffu, s, d);
        const float m_est = s * 0.0016511f;          // 0.84536/512
        const float stepk = m_est * 0.0045548f;      // sigma/(512*f_med)

        unsigned lo = 0u, hi = 0x7f800000u;          // cnt(lo)=0, cnt(+inf)=512
        int nlo = 0, nhi = 512;
        const int R = 255;
        float s255;
        float pnewton = m_est;
        int it = 0;
        while (true) {
            if (nlo == R) {
                unsigned mb = 0x7f800000u;
#pragma unroll
                for (int i = 0; i < 16; i++) {
                    unsigned ua = __float_as_uint(cd1[i]) & 0x7fffffffu;
                    if (ua >= lo) mb = min(mb, ua);
                }
                s255 = __uint_as_float(__reduce_min_sync(0xffffffffu, mb));
                break;
            }
            if (nhi == R + 1) {
                unsigned mb = 0u;
#pragma unroll
                for (int i = 0; i < 16; i++) {
                    unsigned ua = __float_as_uint(cd1[i]) & 0x7fffffffu;
                    if (ua < hi) mb = max(mb, ua);
                }
                s255 = __uint_as_float(__reduce_max_sync(0xffffffffu, mb));
                break;
            }
            if (hi - lo <= 1u) { s255 = __uint_as_float(lo); break; }

            unsigned p;
            if (it < 8) p = __float_as_uint(fmaxf(pnewton, 0.0f));
            else        p = lo + ((hi - lo) >> 1);   // safeguard bisection
            if (p <= lo) p = lo + 1u;
            if (p >= hi) p = hi - 1u;
            const float pf = __uint_as_float(p);

            float fc = 0.f;
#pragma unroll
            for (int i = 0; i < 16; i++) fc += (float)(fabsf(cd1[i]) < pf);
            const int c = (int)__reduce_add_sync(0xffffffffu, (unsigned)fc);
            if (c <= R) { lo = p; nlo = c; } else { hi = p; nhi = c; }
            pnewton = fmaf(255.5f - (float)c, stepk, pf);
            it++;
        }

        // rank 256
        float fle = 0.f;
#pragma unroll
        for (int i = 0; i < 16; i++) fle += (float)(fabsf(cd1[i]) <= s255);
        const int cle = (int)__reduce_add_sync(0xffffffffu, (unsigned)fle);
        float s256;
        if (cle >= 257) {
            s256 = s255;
        } else {
            const unsigned sb = __float_as_uint(s255);
            unsigned mb = 0x7f800000u;
#pragma unroll
            for (int i = 0; i < 16; i++) {
                unsigned ua = __float_as_uint(cd1[i]) & 0x7fffffffu;
                if (ua > sb) mb = min(mb, ua);
            }
            s256 = __uint_as_float(__reduce_min_sync(0xffffffffu, mb));
        }

        // thresholds (true scale), folded into primed (unnormalized) domain
        const float median = 0.5f * (s255 + s256) * 0.70710678118654752440f;
        const float lamda  = (median / 0.6745f) * 3.7232974f;
        const float t1h = lamda * 0.70710678f;   // 0.5*(lamda)/C
        const float t2p = lamda * 1.26185951f;   // (lamda/log2(3))/C^2
        const float t3p = lamda * 1.41421356f;   // (lamda*0.5)/C^3

        // ---- inverse: unpark + reconstruct + store ----
        float4* outr = ob + (size_t)row * 256;
#pragma unroll
        for (int i = 0; i < 8; i++) {
            float cd2 = park[(i)      * 32 + lane];
            float ca3 = park[(8 + i)  * 32 + lane];
            float cd3 = park[(16 + i) * 32 + lane];

            float s3 = copysignf(fmaxf(fabsf(cd3) - t3p, 0.0f), cd3);
            float e = ca3 + s3;
            float o = ca3 - s3;
            float up = __shfl_up_sync(0xffffffffu, o, 1);
            float u = (lane & 1) ? up : e;

            float s2 = copysignf(fmaxf(fabsf(cd2) - t2p, 0.0f), cd2);
            float va = fmaf(u, 0.5f,  s2);
            float vb = fmaf(u, 0.5f, -s2);

            float s1a = copysignf(fmaxf(fmaf(fabsf(cd1[2*i]),   0.5f, -t1h), 0.0f), cd1[2*i]);
            float s1b = copysignf(fmaxf(fmaf(fabsf(cd1[2*i+1]), 0.5f, -t1h), 0.0f), cd1[2*i+1]);
            float4 w;
            w.x = fmaf(va, 0.25f,  s1a);
            w.y = fmaf(va, 0.25f, -s1a);
            w.z = fmaf(vb, 0.25f,  s1b);
            w.w = fmaf(vb, 0.25f, -s1b);
            __stcs(&outr[i * 32 + lane], w);
        }

        if (nxt >= nrows) break;
        row = nxt;
    }
}

extern "C" void kernel_launch(void* const* d_in, const int* in_sizes, int n_in,
                              void* d_out, int out_size)
{
    const float* x = (const float*)d_in[0];
    float* out = (float*)d_out;
    int n = in_sizes[0];
    int nrows = n >> 10;                  // L = 1024 per row
    int blocks = (nrows + 31) / 32;       // ~4 rows per warp (2048 CTAs @65536 rows)
    if (blocks < 1) blocks = 1;
    const int dsm_bytes = 8 * 256 * 16 + 8 * 24 * 32 * 4;   // 32KB buf + 24KB park
    cudaFuncSetAttribute(wavelet_rows_kernel,
                         cudaFuncAttributeMaxDynamicSharedMemorySize, dsm_bytes);
    wavelet_rows_kernel<<<blocks, 256, dsm_bytes>>>(x, out, nrows);
}